// round 3
// baseline (speedup 1.0000x reference)
#include <cuda_runtime.h>

#define NATOM 384
#define NB 8
#define KNBR 383
#define NT 4
#define M0 25
#define M1 50
#define M2 100
#define J0P 28    // padded M0 for float4 j-chunks
#define J1P 52    // padded M1 for float4 j-chunks
#define ET 40     // edges per tile
#define ER 8      // edges per thread
#define EG 5      // edge groups
#define TPB 128

__device__ int g_perm[NATOM * KNBR];
__device__ int g_boff[NATOM * NT];

__global__ void prep_kernel(const int* __restrict__ types) {
    __shared__ int ts[NATOM];
    int t = threadIdx.x;
    ts[t] = types[t];
    __syncthreads();
    int cnt[NT] = {0, 0, 0, 0};
    for (int j = 0; j < NATOM; j++)
        if (j != t) cnt[ts[j]]++;
    int off[NT];
    off[0] = 0;
    for (int c = 1; c < NT; c++) off[c] = off[c - 1] + cnt[c - 1];
    for (int c = 0; c < NT; c++) g_boff[t * NT + c] = off[c];
    for (int j = 0; j < NATOM; j++)
        if (j != t) {
            int c = ts[j];
            g_perm[t * KNBR + off[c]++] = j;
        }
}

__device__ __forceinline__ float tanh_m(float x) {
    float y;
    asm("tanh.approx.f32 %0, %1;" : "=f"(y) : "f"(x));
    return y;
}

// smem pool offsets (floats)
#define O_W2  0                      // W2^T [M2][J1P] = 5200
#define O_W1  (O_W2 + M2 * J1P)      // W1^T [M1][J0P] = 1400
#define O_H1  (O_W1 + M1 * J0P)      // h1 [J1P][ET]  = 2080
#define O_H0  (O_H1 + J1P * ET)      // h0 [J0P][ET]  = 1120
#define O_AE  (O_H0 + J0P * ET)      // aes [3][ET]   = 120
#define O_XS  (O_AE + 3 * ET)        // xs [ET]       = 40
#define O_W0  (O_XS + ET)            // 28
#define O_B0  (O_W0 + 28)            // 28
#define O_B1  (O_B0 + 28)            // 52
#define O_B2  (O_B1 + 52)            // 100
#define POOL  (O_B2 + 100)           // 10168 floats = 40672 B
// Sred[EG][300] + Sfin[300] alias onto O_W2 after main loop (1800 < 5200)

__global__ __launch_bounds__(TPB, 5) void main_kernel(
    const float* __restrict__ coords, const int* __restrict__ types,
    const float* __restrict__ W0, const float* __restrict__ b0,
    const float* __restrict__ W1, const float* __restrict__ b1,
    const float* __restrict__ W2, const float* __restrict__ b2,
    float* __restrict__ out)
{
    __shared__ __align__(16) float P[POOL];
    float* const W2s = P + O_W2;
    float* const W1s = P + O_W1;
    float* const h1s = P + O_H1;
    float* const h0s = P + O_H0;
    float* const aes = P + O_AE;
    float* const xs  = P + O_XS;
    float* const W0s = P + O_W0;
    float* const b0s = P + O_B0;
    float* const b1s = P + O_B1;
    float* const b2s = P + O_B2;

    int t = threadIdx.x;
    int bid = blockIdx.x;
    int n = bid % NATOM;
    int b = bid / NATOM;
    int tc = __ldg(&types[n]);
    float cx = __ldg(&coords[(b * NATOM + n) * 3 + 0]);
    float cy = __ldg(&coords[(b * NATOM + n) * 3 + 1]);
    float cz = __ldg(&coords[(b * NATOM + n) * 3 + 2]);

    int gm = t % 25;
    int ge = t / 25;          // 0..4 for t<125
    int e0 = ge * ER;

    // zero pad rows (h0 rows 25..27, h1 rows 50,51) — never written again
    for (int i = t; i < 3 * ET; i += TPB) h0s[M0 * ET + i] = 0.f;
    for (int i = t; i < 2 * ET; i += TPB) h1s[M1 * ET + i] = 0.f;

    float Sp[4][3];
#pragma unroll
    for (int q = 0; q < 4; q++) { Sp[q][0] = 0.f; Sp[q][1] = 0.f; Sp[q][2] = 0.f; }

    for (int tn = 0; tn < NT; tn++) {
        __syncthreads();
        int idx = tc * NT + tn;
        // W2^T: coalesced global read, strided smem write
        for (int k = t; k < M1 * M2; k += TPB) {
            int j = k / M2, m = k % M2;
            W2s[m * J1P + j] = W2[(size_t)idx * (M1 * M2) + k];
        }
        for (int k = t; k < M2 * 2; k += TPB) {          // zero pad cols j=50,51
            int m = k >> 1;
            W2s[m * J1P + M1 + (k & 1)] = 0.f;
        }
        for (int k = t; k < M0 * M1; k += TPB) {
            int j = k / M1, o = k % M1;
            W1s[o * J0P + j] = W1[(size_t)idx * (M0 * M1) + k];
        }
        for (int k = t; k < M1 * 3; k += TPB) {          // zero pad cols j=25..27
            int o = k / 3;
            W1s[o * J0P + M0 + (k % 3)] = 0.f;
        }
        if (t < M0) { W0s[t] = W0[idx * M0 + t]; b0s[t] = b0[idx * M0 + t]; }
        if (t < M1) b1s[t] = b1[idx * M1 + t];
        if (t < M2) b2s[t] = b2[idx * M2 + t];
        __syncthreads();

        int bs = g_boff[n * NT + tn];
        int be = (tn == NT - 1) ? KNBR : g_boff[n * NT + tn + 1];
        int cnt = be - bs;
        const int* pbase = g_perm + n * KNBR + bs;

        for (int t0 = 0; t0 < cnt; t0 += ET) {
            // ---- Stage 0a: geometry (40 threads) ----
            if (t < ET) {
                int gi = t0 + t;
                float x = 0.f, ax = 0.f, ay = 0.f, az = 0.f;
                if (gi < cnt) {
                    int j = __ldg(&pbase[gi]);
                    float rx = cx - __ldg(&coords[(b * NATOM + j) * 3 + 0]);
                    float ry = cy - __ldg(&coords[(b * NATOM + j) * 3 + 1]);
                    float rz = cz - __ldg(&coords[(b * NATOM + j) * 3 + 2]);
                    float d2 = rx * rx + ry * ry + rz * rz;
                    x = rsqrtf(d2);
                    float i2 = x * x;
                    ax = rx * i2; ay = ry * i2; az = rz * i2;
                }
                xs[t] = x;
                aes[0 * ET + t] = ax;
                aes[1 * ET + t] = ay;
                aes[2 * ET + t] = az;
            }
            __syncthreads();

            // ---- Stage 0b: layer0 (all 128 threads; padded edges harmless: aes=0) ----
#pragma unroll
            for (int k = t; k < M0 * ET; k += TPB) {
                int e = k / M0, i = k - e * M0;
                h0s[i * ET + e] = tanh_m(fmaf(xs[e], W0s[i], b0s[i]));
            }
            __syncthreads();

            // ---- Stage 1: 25->50, float4 weights over j ----
            if (t < 125) {
                float acc0[ER], acc1[ER];
                float bb0 = b1s[gm], bb1 = b1s[gm + 25];
#pragma unroll
                for (int e = 0; e < ER; e++) { acc0[e] = bb0; acc1[e] = bb1; }
#pragma unroll
                for (int jc = 0; jc < J0P / 4; jc++) {
                    float4 w0 = *(const float4*)(W1s + gm * J0P + jc * 4);
                    float4 w1 = *(const float4*)(W1s + (gm + 25) * J0P + jc * 4);
                    float wa0[4] = {w0.x, w0.y, w0.z, w0.w};
                    float wa1[4] = {w1.x, w1.y, w1.z, w1.w};
#pragma unroll
                    for (int u = 0; u < 4; u++) {
                        int j = jc * 4 + u;
                        float4 A = *(const float4*)(h0s + j * ET + e0);
                        float4 Bv = *(const float4*)(h0s + j * ET + e0 + 4);
                        acc0[0] = fmaf(wa0[u], A.x, acc0[0]); acc1[0] = fmaf(wa1[u], A.x, acc1[0]);
                        acc0[1] = fmaf(wa0[u], A.y, acc0[1]); acc1[1] = fmaf(wa1[u], A.y, acc1[1]);
                        acc0[2] = fmaf(wa0[u], A.z, acc0[2]); acc1[2] = fmaf(wa1[u], A.z, acc1[2]);
                        acc0[3] = fmaf(wa0[u], A.w, acc0[3]); acc1[3] = fmaf(wa1[u], A.w, acc1[3]);
                        acc0[4] = fmaf(wa0[u], Bv.x, acc0[4]); acc1[4] = fmaf(wa1[u], Bv.x, acc1[4]);
                        acc0[5] = fmaf(wa0[u], Bv.y, acc0[5]); acc1[5] = fmaf(wa1[u], Bv.y, acc1[5]);
                        acc0[6] = fmaf(wa0[u], Bv.z, acc0[6]); acc1[6] = fmaf(wa1[u], Bv.z, acc1[6]);
                        acc0[7] = fmaf(wa0[u], Bv.w, acc0[7]); acc1[7] = fmaf(wa1[u], Bv.w, acc1[7]);
                    }
                }
#pragma unroll
                for (int e = 0; e < ER; e++) {
                    float h0v = h0s[gm * ET + e0 + e];
                    h1s[gm * ET + e0 + e] = tanh_m(acc0[e]) + h0v;
                    h1s[(gm + 25) * ET + e0 + e] = tanh_m(acc1[e]) + h0v;
                }
            }
            __syncthreads();

            // ---- Stage 2: 50->100 + S accumulation ----
            if (t < 125) {
                float acc[4][ER];
#pragma unroll
                for (int q = 0; q < 4; q++) {
                    float bb = b2s[gm + 25 * q];
#pragma unroll
                    for (int e = 0; e < ER; e++) acc[q][e] = bb;
                }
#pragma unroll
                for (int jc = 0; jc < J1P / 4; jc++) {
                    float4 w0 = *(const float4*)(W2s + gm * J1P + jc * 4);
                    float4 w1 = *(const float4*)(W2s + (gm + 25) * J1P + jc * 4);
                    float4 w2v = *(const float4*)(W2s + (gm + 50) * J1P + jc * 4);
                    float4 w3 = *(const float4*)(W2s + (gm + 75) * J1P + jc * 4);
                    float wa0[4] = {w0.x, w0.y, w0.z, w0.w};
                    float wa1[4] = {w1.x, w1.y, w1.z, w1.w};
                    float wa2[4] = {w2v.x, w2v.y, w2v.z, w2v.w};
                    float wa3[4] = {w3.x, w3.y, w3.z, w3.w};
#pragma unroll
                    for (int u = 0; u < 4; u++) {
                        int j = jc * 4 + u;
                        float4 A = *(const float4*)(h1s + j * ET + e0);
                        float4 Bv = *(const float4*)(h1s + j * ET + e0 + 4);
                        float hv[8] = {A.x, A.y, A.z, A.w, Bv.x, Bv.y, Bv.z, Bv.w};
#pragma unroll
                        for (int e = 0; e < ER; e++) {
                            acc[0][e] = fmaf(wa0[u], hv[e], acc[0][e]);
                            acc[1][e] = fmaf(wa1[u], hv[e], acc[1][e]);
                            acc[2][e] = fmaf(wa2[u], hv[e], acc[2][e]);
                            acc[3][e] = fmaf(wa3[u], hv[e], acc[3][e]);
                        }
                    }
                }
                float r0[ER], r1[ER], a0[ER], a1[ER], a2[ER];
#pragma unroll
                for (int e = 0; e < ER; e++) {
                    r0[e] = h1s[gm * ET + e0 + e];
                    r1[e] = h1s[(gm + 25) * ET + e0 + e];
                    a0[e] = aes[0 * ET + e0 + e];
                    a1[e] = aes[1 * ET + e0 + e];
                    a2[e] = aes[2 * ET + e0 + e];
                }
#pragma unroll
                for (int q = 0; q < 4; q++) {
#pragma unroll
                    for (int e = 0; e < ER; e++) {
                        float res = (q & 1) ? r1[e] : r0[e];
                        float v = tanh_m(acc[q][e]) + res;
                        Sp[q][0] = fmaf(a0[e], v, Sp[q][0]);
                        Sp[q][1] = fmaf(a1[e], v, Sp[q][1]);
                        Sp[q][2] = fmaf(a2[e], v, Sp[q][2]);
                    }
                }
            }
            __syncthreads();
        }
    }

    // ---- Final reduction (alias Sred/Sfin onto W2s region; last sync above guards) ----
    float* const Sred = P;                 // [EG][M2*3]
    float* const Sfin = P + EG * M2 * 3;   // [M2*3]
    if (t < 125) {
#pragma unroll
        for (int q = 0; q < 4; q++) {
            Sred[ge * (M2 * 3) + (gm + 25 * q) * 3 + 0] = Sp[q][0];
            Sred[ge * (M2 * 3) + (gm + 25 * q) * 3 + 1] = Sp[q][1];
            Sred[ge * (M2 * 3) + (gm + 25 * q) * 3 + 2] = Sp[q][2];
        }
    }
    __syncthreads();
    if (t < M2) {
        float s0 = 0.f, s1 = 0.f, s2 = 0.f;
#pragma unroll
        for (int g = 0; g < EG; g++) {
            s0 += Sred[g * (M2 * 3) + t * 3 + 0];
            s1 += Sred[g * (M2 * 3) + t * 3 + 1];
            s2 += Sred[g * (M2 * 3) + t * 3 + 2];
        }
        Sfin[t * 3 + 0] = s0; Sfin[t * 3 + 1] = s1; Sfin[t * 3 + 2] = s2;
    }
    __syncthreads();
    if (t < M2) {
        float s0 = Sfin[t * 3 + 0], s1 = Sfin[t * 3 + 1], s2 = Sfin[t * 3 + 2];
        float* o = out + (size_t)bid * (M2 * 4) + t * 4;
#pragma unroll
        for (int a = 0; a < 4; a++) {
            o[a] = s0 * Sfin[a * 3 + 0] + s1 * Sfin[a * 3 + 1] + s2 * Sfin[a * 3 + 2];
        }
    }
}

extern "C" void kernel_launch(void* const* d_in, const int* in_sizes, int n_in,
                              void* d_out, int out_size)
{
    const float* coords = (const float*)d_in[0];
    const int*   types  = (const int*)d_in[1];
    const float* W0     = (const float*)d_in[2];
    const float* b0     = (const float*)d_in[3];
    const float* W1     = (const float*)d_in[4];
    const float* b1     = (const float*)d_in[5];
    const float* W2     = (const float*)d_in[6];
    const float* b2     = (const float*)d_in[7];
    float* out = (float*)d_out;

    prep_kernel<<<1, NATOM>>>(types);
    main_kernel<<<NB * NATOM, TPB>>>(coords, types, W0, b0, W1, b1, W2, b2, out);
}

// round 4
// speedup vs baseline: 1.0740x; 1.0740x over previous
#include <cuda_runtime.h>

#define NATOM 384
#define NB 8
#define KNBR 383
#define NT 4
#define M0 25
#define M1 50
#define M2 100
#define ET 40
#define ER 8
#define EG 5
#define TPB 128

__device__ int g_perm[NATOM * KNBR];
__device__ int g_boff[NATOM * NT];

__global__ void prep_kernel(const int* __restrict__ types) {
    __shared__ int ts[NATOM];
    int t = threadIdx.x;
    ts[t] = types[t];
    __syncthreads();
    int cnt[NT] = {0, 0, 0, 0};
    for (int j = 0; j < NATOM; j++)
        if (j != t) cnt[ts[j]]++;
    int off[NT];
    off[0] = 0;
    for (int c = 1; c < NT; c++) off[c] = off[c - 1] + cnt[c - 1];
    for (int c = 0; c < NT; c++) g_boff[t * NT + c] = off[c];
    for (int j = 0; j < NATOM; j++)
        if (j != t) {
            int c = ts[j];
            g_perm[t * KNBR + off[c]++] = j;
        }
}

__device__ __forceinline__ float tanh_m(float x) {
    float y;
    asm("tanh.approx.f32 %0, %1;" : "=f"(y) : "f"(x));
    return y;
}

// smem pool offsets (floats), all float4-aligned where needed
#define O_W2  0                      // W2r [M1][25][4] = 5000
#define O_W1  5000                   // W1r [M0][25][2] = 1250
#define O_H1  6252                   // h1 [M1][ET] = 2000
#define O_H0  8252                   // h0 [M0][ET] = 1000
#define O_AE  9252                   // aes [3][ET] = 120
#define O_XS  9372                   // xs [ET] = 40
#define O_W0  9412                   // 25 (pad to 28)
#define O_B0  9440                   // 25 (pad to 28)
#define O_B1  9468                   // b1r [25][2] = 50 (pad 52)
#define O_B2  9520                   // b2r [25][4] = 100
#define POOL  9620                   // 38480 B

__global__ __launch_bounds__(TPB, 5) void main_kernel(
    const float* __restrict__ coords, const int* __restrict__ types,
    const float* __restrict__ W0, const float* __restrict__ b0,
    const float* __restrict__ W1, const float* __restrict__ b1,
    const float* __restrict__ W2, const float* __restrict__ b2,
    float* __restrict__ out)
{
    __shared__ __align__(16) float P[POOL];
    float* const W2r = P + O_W2;
    float* const W1r = P + O_W1;
    float* const h1s = P + O_H1;
    float* const h0s = P + O_H0;
    float* const aes = P + O_AE;
    float* const xs  = P + O_XS;
    float* const W0s = P + O_W0;
    float* const b0s = P + O_B0;
    float* const b1r = P + O_B1;
    float* const b2r = P + O_B2;

    int t = threadIdx.x;
    int bid = blockIdx.x;
    int n = bid % NATOM;
    int b = bid / NATOM;
    int tc = __ldg(&types[n]);
    float cx = __ldg(&coords[(b * NATOM + n) * 3 + 0]);
    float cy = __ldg(&coords[(b * NATOM + n) * 3 + 1]);
    float cz = __ldg(&coords[(b * NATOM + n) * 3 + 2]);

    int gm = t % 25;
    int ge = t / 25;          // 0..4 for t<125
    int e0 = ge * ER;

    float Sp[4][3];
#pragma unroll
    for (int q = 0; q < 4; q++) { Sp[q][0] = 0.f; Sp[q][1] = 0.f; Sp[q][2] = 0.f; }

    for (int tn = 0; tn < NT; tn++) {
        __syncthreads();
        int idx = tc * NT + tn;
        // W2r[j][gm][q] <- W2[idx][j][gm + 25q]  (coalesced GMEM reads)
        for (int k = t; k < M1 * M2; k += TPB) {
            int j = k / M2, m = k - (k / M2) * M2;
            int g = m % 25, q = m / 25;
            W2r[j * M2 + g * 4 + q] = W2[(size_t)idx * (M1 * M2) + k];
        }
        // W1r[j][gm][p] <- W1[idx][j][gm + 25p]
        for (int k = t; k < M0 * M1; k += TPB) {
            int j = k / M1, m = k - (k / M1) * M1;
            int g = m % 25, p = m / 25;
            W1r[j * M1 + g * 2 + p] = W1[(size_t)idx * (M0 * M1) + k];
        }
        if (t < M0) { W0s[t] = W0[idx * M0 + t]; b0s[t] = b0[idx * M0 + t]; }
        if (t < M1) { int g = t % 25, p = t / 25; b1r[g * 2 + p] = b1[idx * M1 + t]; }
        if (t < M2) { int g = t % 25, q = t / 25; b2r[g * 4 + q] = b2[idx * M2 + t]; }
        __syncthreads();

        int bs = g_boff[n * NT + tn];
        int be = (tn == NT - 1) ? KNBR : g_boff[n * NT + tn + 1];
        int cnt = be - bs;
        const int* pbase = g_perm + n * KNBR + bs;

        for (int t0 = 0; t0 < cnt; t0 += ET) {
            // ---- Stage 0a: geometry (40 threads) ----
            if (t < ET) {
                int gi = t0 + t;
                float x = 0.f, ax = 0.f, ay = 0.f, az = 0.f;
                if (gi < cnt) {
                    int j = __ldg(&pbase[gi]);
                    float rx = cx - __ldg(&coords[(b * NATOM + j) * 3 + 0]);
                    float ry = cy - __ldg(&coords[(b * NATOM + j) * 3 + 1]);
                    float rz = cz - __ldg(&coords[(b * NATOM + j) * 3 + 2]);
                    float d2 = rx * rx + ry * ry + rz * rz;
                    x = rsqrtf(d2);
                    float i2 = x * x;
                    ax = rx * i2; ay = ry * i2; az = rz * i2;
                }
                xs[t] = x;
                aes[0 * ET + t] = ax;
                aes[1 * ET + t] = ay;
                aes[2 * ET + t] = az;
            }
            __syncthreads();

            // ---- Stage 0b: layer0, all threads, conflict-free (e fast) ----
            // padded edges (x=0) produce tanh(b0) but aes=0 kills their S contribution
#pragma unroll
            for (int k = t; k < M0 * ET; k += TPB) {
                int i = k / ET, e = k - i * ET;
                h0s[i * ET + e] = tanh_m(fmaf(xs[e], W0s[i], b0s[i]));
            }
            __syncthreads();

            // ---- Stage 1: 25->50 ----
            if (t < 125) {
                float acc0[ER], acc1[ER];
                float2 bb = *(const float2*)(b1r + gm * 2);
#pragma unroll
                for (int e = 0; e < ER; e++) { acc0[e] = bb.x; acc1[e] = bb.y; }
#pragma unroll 5
                for (int j = 0; j < M0; j++) {
                    float2 w = *(const float2*)(W1r + j * M1 + gm * 2);
                    float4 A = *(const float4*)(h0s + j * ET + e0);
                    float4 Bv = *(const float4*)(h0s + j * ET + e0 + 4);
                    acc0[0] = fmaf(w.x, A.x, acc0[0]); acc1[0] = fmaf(w.y, A.x, acc1[0]);
                    acc0[1] = fmaf(w.x, A.y, acc0[1]); acc1[1] = fmaf(w.y, A.y, acc1[1]);
                    acc0[2] = fmaf(w.x, A.z, acc0[2]); acc1[2] = fmaf(w.y, A.z, acc1[2]);
                    acc0[3] = fmaf(w.x, A.w, acc0[3]); acc1[3] = fmaf(w.y, A.w, acc1[3]);
                    acc0[4] = fmaf(w.x, Bv.x, acc0[4]); acc1[4] = fmaf(w.y, Bv.x, acc1[4]);
                    acc0[5] = fmaf(w.x, Bv.y, acc0[5]); acc1[5] = fmaf(w.y, Bv.y, acc1[5]);
                    acc0[6] = fmaf(w.x, Bv.z, acc0[6]); acc1[6] = fmaf(w.y, Bv.z, acc1[6]);
                    acc0[7] = fmaf(w.x, Bv.w, acc0[7]); acc1[7] = fmaf(w.y, Bv.w, acc1[7]);
                }
#pragma unroll
                for (int e = 0; e < ER; e++) {
                    float h0v = h0s[gm * ET + e0 + e];
                    h1s[gm * ET + e0 + e] = tanh_m(acc0[e]) + h0v;
                    h1s[(gm + 25) * ET + e0 + e] = tanh_m(acc1[e]) + h0v;
                }
            }
            __syncthreads();

            // ---- Stage 2: 50->100 + S accumulation ----
            if (t < 125) {
                float acc[4][ER];
                float4 bb = *(const float4*)(b2r + gm * 4);
                float bq[4] = {bb.x, bb.y, bb.z, bb.w};
#pragma unroll
                for (int q = 0; q < 4; q++)
#pragma unroll
                    for (int e = 0; e < ER; e++) acc[q][e] = bq[q];
#pragma unroll 5
                for (int j = 0; j < M1; j++) {
                    float4 w = *(const float4*)(W2r + j * M2 + gm * 4);
                    float4 A = *(const float4*)(h1s + j * ET + e0);
                    float4 Bv = *(const float4*)(h1s + j * ET + e0 + 4);
                    float hv[8] = {A.x, A.y, A.z, A.w, Bv.x, Bv.y, Bv.z, Bv.w};
#pragma unroll
                    for (int e = 0; e < ER; e++) {
                        acc[0][e] = fmaf(w.x, hv[e], acc[0][e]);
                        acc[1][e] = fmaf(w.y, hv[e], acc[1][e]);
                        acc[2][e] = fmaf(w.z, hv[e], acc[2][e]);
                        acc[3][e] = fmaf(w.w, hv[e], acc[3][e]);
                    }
                }
                float r0[ER], r1[ER], a0[ER], a1[ER], a2[ER];
#pragma unroll
                for (int e = 0; e < ER; e++) {
                    r0[e] = h1s[gm * ET + e0 + e];
                    r1[e] = h1s[(gm + 25) * ET + e0 + e];
                    a0[e] = aes[0 * ET + e0 + e];
                    a1[e] = aes[1 * ET + e0 + e];
                    a2[e] = aes[2 * ET + e0 + e];
                }
#pragma unroll
                for (int q = 0; q < 4; q++) {
#pragma unroll
                    for (int e = 0; e < ER; e++) {
                        float res = (q & 1) ? r1[e] : r0[e];
                        float v = tanh_m(acc[q][e]) + res;
                        Sp[q][0] = fmaf(a0[e], v, Sp[q][0]);
                        Sp[q][1] = fmaf(a1[e], v, Sp[q][1]);
                        Sp[q][2] = fmaf(a2[e], v, Sp[q][2]);
                    }
                }
            }
            __syncthreads();
        }
    }

    // ---- Final reduction (alias onto weight region; guarded by last sync) ----
    float* const Sred = P;                 // [EG][M2*3]
    float* const Sfin = P + EG * M2 * 3;
    if (t < 125) {
#pragma unroll
        for (int q = 0; q < 4; q++) {
            Sred[ge * (M2 * 3) + (gm + 25 * q) * 3 + 0] = Sp[q][0];
            Sred[ge * (M2 * 3) + (gm + 25 * q) * 3 + 1] = Sp[q][1];
            Sred[ge * (M2 * 3) + (gm + 25 * q) * 3 + 2] = Sp[q][2];
        }
    }
    __syncthreads();
    if (t < M2) {
        float s0 = 0.f, s1 = 0.f, s2 = 0.f;
#pragma unroll
        for (int g = 0; g < EG; g++) {
            s0 += Sred[g * (M2 * 3) + t * 3 + 0];
            s1 += Sred[g * (M2 * 3) + t * 3 + 1];
            s2 += Sred[g * (M2 * 3) + t * 3 + 2];
        }
        Sfin[t * 3 + 0] = s0; Sfin[t * 3 + 1] = s1; Sfin[t * 3 + 2] = s2;
    }
    __syncthreads();
    if (t < M2) {
        float s0 = Sfin[t * 3 + 0], s1 = Sfin[t * 3 + 1], s2 = Sfin[t * 3 + 2];
        float4 o;
        o.x = s0 * Sfin[0] + s1 * Sfin[1] + s2 * Sfin[2];
        o.y = s0 * Sfin[3] + s1 * Sfin[4] + s2 * Sfin[5];
        o.z = s0 * Sfin[6] + s1 * Sfin[7] + s2 * Sfin[8];
        o.w = s0 * Sfin[9] + s1 * Sfin[10] + s2 * Sfin[11];
        *(float4*)(out + (size_t)bid * (M2 * 4) + t * 4) = o;
    }
}

extern "C" void kernel_launch(void* const* d_in, const int* in_sizes, int n_in,
                              void* d_out, int out_size)
{
    const float* coords = (const float*)d_in[0];
    const int*   types  = (const int*)d_in[1];
    const float* W0     = (const float*)d_in[2];
    const float* b0     = (const float*)d_in[3];
    const float* W1     = (const float*)d_in[4];
    const float* b1     = (const float*)d_in[5];
    const float* W2     = (const float*)d_in[6];
    const float* b2     = (const float*)d_in[7];
    float* out = (float*)d_out;

    prep_kernel<<<1, NATOM>>>(types);
    main_kernel<<<NB * NATOM, TPB>>>(coords, types, W0, b0, W1, b1, W2, b2, out);
}

// round 5
// speedup vs baseline: 1.2349x; 1.1498x over previous
#include <cuda_runtime.h>

#define NATOM 384
#define NB 8
#define KNBR 383
#define NT 4
#define M0 25
#define M1 50
#define M2 100
#define ET 40
#define ER 8
#define EG 5
#define TPB 128
#define HST 44   // padded row stride for h0/h1 (conflict-free STS.128, 16B aligned)

__device__ int g_perm[NATOM * KNBR];
__device__ int g_boff[NATOM * NT];

__global__ void prep_kernel(const int* __restrict__ types) {
    __shared__ int ts[NATOM];
    int t = threadIdx.x;
    ts[t] = types[t];
    __syncthreads();
    int cnt[NT] = {0, 0, 0, 0};
    for (int j = 0; j < NATOM; j++)
        if (j != t) cnt[ts[j]]++;
    int off[NT];
    off[0] = 0;
    for (int c = 1; c < NT; c++) off[c] = off[c - 1] + cnt[c - 1];
    for (int c = 0; c < NT; c++) g_boff[t * NT + c] = off[c];
    for (int j = 0; j < NATOM; j++)
        if (j != t) {
            int c = ts[j];
            g_perm[t * KNBR + off[c]++] = j;
        }
}

__device__ __forceinline__ float tanh_m(float x) {
    float y;
    asm("tanh.approx.f32 %0, %1;" : "=f"(y) : "f"(x));
    return y;
}

// smem pool offsets (floats)
#define O_W2  0                      // W2r [M1][25][4] = 5000
#define O_W1  5000                   // W1r [M0][25][2] = 1250
#define O_H1  6252                   // h1 [M1][HST] = 2200
#define O_H0  8452                   // h0 [M0][HST] = 1100
#define O_AE  9552                   // aes [3][ET] = 120
#define O_XS  9672                   // xs [ET] = 40
#define O_W0  9712                   // 28
#define O_B0  9740                   // 28
#define O_B1  9768                   // b1r [25][2] = 52
#define O_B2  9820                   // b2r [25][4] = 100
#define POOL  9920                   // 39680 B

__global__ __launch_bounds__(TPB, 5) void main_kernel(
    const float* __restrict__ coords, const int* __restrict__ types,
    const float* __restrict__ W0, const float* __restrict__ b0,
    const float* __restrict__ W1, const float* __restrict__ b1,
    const float* __restrict__ W2, const float* __restrict__ b2,
    float* __restrict__ out)
{
    __shared__ __align__(16) float P[POOL];
    float* const W2r = P + O_W2;
    float* const W1r = P + O_W1;
    float* const h1s = P + O_H1;
    float* const h0s = P + O_H0;
    float* const aes = P + O_AE;
    float* const xs  = P + O_XS;
    float* const W0s = P + O_W0;
    float* const b0s = P + O_B0;
    float* const b1r = P + O_B1;
    float* const b2r = P + O_B2;

    int t = threadIdx.x;
    int bid = blockIdx.x;
    int n = bid % NATOM;
    int b = bid / NATOM;
    int tc = __ldg(&types[n]);
    float cx = __ldg(&coords[(b * NATOM + n) * 3 + 0]);
    float cy = __ldg(&coords[(b * NATOM + n) * 3 + 1]);
    float cz = __ldg(&coords[(b * NATOM + n) * 3 + 2]);

    int gm = t % 25;
    int ge = t / 25;          // 0..4 for t<125
    int e0 = ge * ER;
    bool act = (t < 125);

    float Sp[4][3];
#pragma unroll
    for (int q = 0; q < 4; q++) { Sp[q][0] = 0.f; Sp[q][1] = 0.f; Sp[q][2] = 0.f; }

    for (int tn = 0; tn < NT; tn++) {
        __syncthreads();
        int idx = tc * NT + tn;
        // W2r[j][gm][q] <- W2[idx][j][gm + 25q]  (coalesced GMEM reads)
        for (int k = t; k < M1 * M2; k += TPB) {
            int j = k / M2, m = k - j * M2;
            int g = m % 25, q = m / 25;
            W2r[j * M2 + g * 4 + q] = W2[(size_t)idx * (M1 * M2) + k];
        }
        // W1r[j][gm][p]
        for (int k = t; k < M0 * M1; k += TPB) {
            int j = k / M1, m = k - j * M1;
            int g = m % 25, p = m / 25;
            W1r[j * M1 + g * 2 + p] = W1[(size_t)idx * (M0 * M1) + k];
        }
        if (t < M0) { W0s[t] = W0[idx * M0 + t]; b0s[t] = b0[idx * M0 + t]; }
        if (t < M1) { int g = t % 25, p = t / 25; b1r[g * 2 + p] = b1[idx * M1 + t]; }
        if (t < M2) { int g = t % 25, q = t / 25; b2r[g * 4 + q] = b2[idx * M2 + t]; }
        __syncthreads();

        int bs = g_boff[n * NT + tn];
        int be = (tn == NT - 1) ? KNBR : g_boff[n * NT + tn + 1];
        int cnt = be - bs;
        const int* pbase = g_perm + n * KNBR + bs;

        for (int t0 = 0; t0 < cnt; t0 += ET) {
            // ---- Stage 0a: geometry (40 threads) ----
            if (t < ET) {
                int gi = t0 + t;
                float x = 0.f, ax = 0.f, ay = 0.f, az = 0.f;
                if (gi < cnt) {
                    int j = __ldg(&pbase[gi]);
                    float rx = cx - __ldg(&coords[(b * NATOM + j) * 3 + 0]);
                    float ry = cy - __ldg(&coords[(b * NATOM + j) * 3 + 1]);
                    float rz = cz - __ldg(&coords[(b * NATOM + j) * 3 + 2]);
                    float d2 = rx * rx + ry * ry + rz * rz;
                    x = rsqrtf(d2);
                    float i2 = x * x;
                    ax = rx * i2; ay = ry * i2; az = rz * i2;
                }
                xs[t] = x;
                aes[0 * ET + t] = ax;
                aes[1 * ET + t] = ay;
                aes[2 * ET + t] = az;
            }
            __syncthreads();

            float h0v[ER];
            // ---- Stage 0b: layer0, o-major: thread owns row gm, edges e0..e0+7 ----
            if (act) {
                float w0v = W0s[gm], b0v = b0s[gm];
#pragma unroll
                for (int e = 0; e < ER; e++)
                    h0v[e] = tanh_m(fmaf(xs[e0 + e], w0v, b0v));
                float4 v0 = make_float4(h0v[0], h0v[1], h0v[2], h0v[3]);
                float4 v1 = make_float4(h0v[4], h0v[5], h0v[6], h0v[7]);
                *(float4*)(h0s + gm * HST + e0) = v0;
                *(float4*)(h0s + gm * HST + e0 + 4) = v1;
            }
            __syncthreads();

            // ---- Stage 1: 25->50 GEMM + residual-S accumulation ----
            if (act) {
                float acc0[ER], acc1[ER];
                float2 bb = *(const float2*)(b1r + gm * 2);
#pragma unroll
                for (int e = 0; e < ER; e++) { acc0[e] = bb.x; acc1[e] = bb.y; }
#pragma unroll 5
                for (int j = 0; j < M0; j++) {
                    float2 w = *(const float2*)(W1r + j * M1 + gm * 2);
                    float4 A = *(const float4*)(h0s + j * HST + e0);
                    float4 Bv = *(const float4*)(h0s + j * HST + e0 + 4);
                    acc0[0] = fmaf(w.x, A.x, acc0[0]); acc1[0] = fmaf(w.y, A.x, acc1[0]);
                    acc0[1] = fmaf(w.x, A.y, acc0[1]); acc1[1] = fmaf(w.y, A.y, acc1[1]);
                    acc0[2] = fmaf(w.x, A.z, acc0[2]); acc1[2] = fmaf(w.y, A.z, acc1[2]);
                    acc0[3] = fmaf(w.x, A.w, acc0[3]); acc1[3] = fmaf(w.y, A.w, acc1[3]);
                    acc0[4] = fmaf(w.x, Bv.x, acc0[4]); acc1[4] = fmaf(w.y, Bv.x, acc1[4]);
                    acc0[5] = fmaf(w.x, Bv.y, acc0[5]); acc1[5] = fmaf(w.y, Bv.y, acc1[5]);
                    acc0[6] = fmaf(w.x, Bv.z, acc0[6]); acc1[6] = fmaf(w.y, Bv.z, acc1[6]);
                    acc0[7] = fmaf(w.x, Bv.w, acc0[7]); acc1[7] = fmaf(w.y, Bv.w, acc1[7]);
                }
                float h1v0[ER], h1v1[ER];
#pragma unroll
                for (int e = 0; e < ER; e++) {
                    h1v0[e] = tanh_m(acc0[e]) + h0v[e];
                    h1v1[e] = tanh_m(acc1[e]) + h0v[e];
                }
                *(float4*)(h1s + gm * HST + e0) = make_float4(h1v0[0], h1v0[1], h1v0[2], h1v0[3]);
                *(float4*)(h1s + gm * HST + e0 + 4) = make_float4(h1v0[4], h1v0[5], h1v0[6], h1v0[7]);
                *(float4*)(h1s + (gm + 25) * HST + e0) = make_float4(h1v1[0], h1v1[1], h1v1[2], h1v1[3]);
                *(float4*)(h1s + (gm + 25) * HST + e0 + 4) = make_float4(h1v1[4], h1v1[5], h1v1[6], h1v1[7]);
                // residual contribution to S (r0 feeds q=0,2 ; r1 feeds q=1,3)
                float R00 = 0.f, R01 = 0.f, R02 = 0.f, R10 = 0.f, R11 = 0.f, R12 = 0.f;
#pragma unroll
                for (int e = 0; e < ER; e++) {
                    float a0 = aes[0 * ET + e0 + e];
                    float a1 = aes[1 * ET + e0 + e];
                    float a2 = aes[2 * ET + e0 + e];
                    R00 = fmaf(a0, h1v0[e], R00); R01 = fmaf(a1, h1v0[e], R01); R02 = fmaf(a2, h1v0[e], R02);
                    R10 = fmaf(a0, h1v1[e], R10); R11 = fmaf(a1, h1v1[e], R11); R12 = fmaf(a2, h1v1[e], R12);
                }
                Sp[0][0] += R00; Sp[0][1] += R01; Sp[0][2] += R02;
                Sp[2][0] += R00; Sp[2][1] += R01; Sp[2][2] += R02;
                Sp[1][0] += R10; Sp[1][1] += R11; Sp[1][2] += R12;
                Sp[3][0] += R10; Sp[3][1] += R11; Sp[3][2] += R12;
            }
            __syncthreads();

            // ---- Stage 2: 50->100 GEMM + tanh-S accumulation ----
            if (act) {
                float acc[4][ER];
                float4 bb = *(const float4*)(b2r + gm * 4);
                float bq[4] = {bb.x, bb.y, bb.z, bb.w};
#pragma unroll
                for (int q = 0; q < 4; q++)
#pragma unroll
                    for (int e = 0; e < ER; e++) acc[q][e] = bq[q];
#pragma unroll 5
                for (int j = 0; j < M1; j++) {
                    float4 w = *(const float4*)(W2r + j * M2 + gm * 4);
                    float4 A = *(const float4*)(h1s + j * HST + e0);
                    float4 Bv = *(const float4*)(h1s + j * HST + e0 + 4);
                    float hv[8] = {A.x, A.y, A.z, A.w, Bv.x, Bv.y, Bv.z, Bv.w};
#pragma unroll
                    for (int e = 0; e < ER; e++) {
                        acc[0][e] = fmaf(w.x, hv[e], acc[0][e]);
                        acc[1][e] = fmaf(w.y, hv[e], acc[1][e]);
                        acc[2][e] = fmaf(w.z, hv[e], acc[2][e]);
                        acc[3][e] = fmaf(w.w, hv[e], acc[3][e]);
                    }
                }
#pragma unroll
                for (int e = 0; e < ER; e++) {
                    float a0 = aes[0 * ET + e0 + e];
                    float a1 = aes[1 * ET + e0 + e];
                    float a2 = aes[2 * ET + e0 + e];
#pragma unroll
                    for (int q = 0; q < 4; q++) {
                        float v = tanh_m(acc[q][e]);
                        Sp[q][0] = fmaf(a0, v, Sp[q][0]);
                        Sp[q][1] = fmaf(a1, v, Sp[q][1]);
                        Sp[q][2] = fmaf(a2, v, Sp[q][2]);
                    }
                }
            }
            __syncthreads();
        }
    }

    // ---- Final reduction (alias onto weight region; guarded by last sync) ----
    float* const Sred = P;                 // [EG][M2*3]
    float* const Sfin = P + EG * M2 * 3;
    if (act) {
#pragma unroll
        for (int q = 0; q < 4; q++) {
            Sred[ge * (M2 * 3) + (gm + 25 * q) * 3 + 0] = Sp[q][0];
            Sred[ge * (M2 * 3) + (gm + 25 * q) * 3 + 1] = Sp[q][1];
            Sred[ge * (M2 * 3) + (gm + 25 * q) * 3 + 2] = Sp[q][2];
        }
    }
    __syncthreads();
    if (t < M2) {
        float s0 = 0.f, s1 = 0.f, s2 = 0.f;
#pragma unroll
        for (int g = 0; g < EG; g++) {
            s0 += Sred[g * (M2 * 3) + t * 3 + 0];
            s1 += Sred[g * (M2 * 3) + t * 3 + 1];
            s2 += Sred[g * (M2 * 3) + t * 3 + 2];
        }
        Sfin[t * 3 + 0] = s0; Sfin[t * 3 + 1] = s1; Sfin[t * 3 + 2] = s2;
    }
    __syncthreads();
    if (t < M2) {
        float s0 = Sfin[t * 3 + 0], s1 = Sfin[t * 3 + 1], s2 = Sfin[t * 3 + 2];
        float4 o;
        o.x = s0 * Sfin[0] + s1 * Sfin[1] + s2 * Sfin[2];
        o.y = s0 * Sfin[3] + s1 * Sfin[4] + s2 * Sfin[5];
        o.z = s0 * Sfin[6] + s1 * Sfin[7] + s2 * Sfin[8];
        o.w = s0 * Sfin[9] + s1 * Sfin[10] + s2 * Sfin[11];
        *(float4*)(out + (size_t)bid * (M2 * 4) + t * 4) = o;
    }
}

extern "C" void kernel_launch(void* const* d_in, const int* in_sizes, int n_in,
                              void* d_out, int out_size)
{
    const float* coords = (const float*)d_in[0];
    const int*   types  = (const int*)d_in[1];
    const float* W0     = (const float*)d_in[2];
    const float* b0     = (const float*)d_in[3];
    const float* W1     = (const float*)d_in[4];
    const float* b1     = (const float*)d_in[5];
    const float* W2     = (const float*)d_in[6];
    const float* b2     = (const float*)d_in[7];
    float* out = (float*)d_out;

    prep_kernel<<<1, NATOM>>>(types);
    main_kernel<<<NB * NATOM, TPB>>>(coords, types, W0, b0, W1, b1, W2, b2, out);
}

// round 6
// speedup vs baseline: 1.2603x; 1.0206x over previous
#include <cuda_runtime.h>

#define NATOM 384
#define NB 8
#define KNBR 383
#define NT 4
#define M0 25
#define M1 50
#define M2 100
#define ET 40
#define ER 8
#define EG 5
#define TPB 128
#define HST 44   // padded row stride for h0/h1 (conflict-free STS.128, 16B aligned)

__device__ int g_perm[NATOM * KNBR];
__device__ int g_boff[NATOM * NT];

__global__ void prep_kernel(const int* __restrict__ types) {
    __shared__ int ts[NATOM];
    int t = threadIdx.x;
    ts[t] = types[t];
    __syncthreads();
    int cnt[NT] = {0, 0, 0, 0};
    for (int j = 0; j < NATOM; j++)
        if (j != t) cnt[ts[j]]++;
    int off[NT];
    off[0] = 0;
    for (int c = 1; c < NT; c++) off[c] = off[c - 1] + cnt[c - 1];
    for (int c = 0; c < NT; c++) g_boff[t * NT + c] = off[c];
    for (int j = 0; j < NATOM; j++)
        if (j != t) {
            int c = ts[j];
            g_perm[t * KNBR + off[c]++] = j;
        }
}

__device__ __forceinline__ float tanh_m(float x) {
    float y;
    asm("tanh.approx.f32 %0, %1;" : "=f"(y) : "f"(x));
    return y;
}

// smem pool offsets (floats)
#define O_W2  0                      // W2r [M1][25][4] = 5000
#define O_W1  5000                   // W1r [M0][25][2] = 1250
#define O_H1  6252                   // h1 [M1][HST] = 2200
#define O_H0  8452                   // h0 [M0][HST] = 1100
#define O_AE  9552                   // aes [3][ET] = 120
#define O_XS  9672                   // xs [ET] = 40
#define O_W0  9712                   // 28
#define O_B0  9740                   // 28
#define O_B1  9768                   // b1r [25][2] = 52
#define O_B2  9820                   // b2r [25][4] = 100
#define POOL  9920                   // 39680 B

__global__ __launch_bounds__(TPB, 5) void main_kernel(
    const float* __restrict__ coords, const int* __restrict__ types,
    const float* __restrict__ W0, const float* __restrict__ b0,
    const float* __restrict__ W1, const float* __restrict__ b1,
    const float* __restrict__ W2, const float* __restrict__ b2,
    float* __restrict__ out)
{
    __shared__ __align__(16) float P[POOL];
    float* const W2r = P + O_W2;
    float* const W1r = P + O_W1;
    float* const h1s = P + O_H1;
    float* const h0s = P + O_H0;
    float* const aes = P + O_AE;
    float* const xs  = P + O_XS;
    float* const W0s = P + O_W0;
    float* const b0s = P + O_B0;
    float* const b1r = P + O_B1;
    float* const b2r = P + O_B2;

    int t = threadIdx.x;
    int bid = blockIdx.x;
    int n = bid % NATOM;
    int b = bid / NATOM;
    int tc = __ldg(&types[n]);
    float cx = __ldg(&coords[(b * NATOM + n) * 3 + 0]);
    float cy = __ldg(&coords[(b * NATOM + n) * 3 + 1]);
    float cz = __ldg(&coords[(b * NATOM + n) * 3 + 2]);

    int gm = t % 25;
    int ge = t / 25;          // 0..4 for t<125
    int e0 = ge * ER;
    bool act = (t < 125);

    // hoisted per-thread base pointers
    const float* const h0base = h0s + e0;
    const float* const h1base = h1s + e0;
    const float* const w1base = W1r + gm * 2;
    const float* const w2base = W2r + gm * 4;
    const float* const aeb = aes + e0;

    float Sp[4][3];
#pragma unroll
    for (int q = 0; q < 4; q++) { Sp[q][0] = 0.f; Sp[q][1] = 0.f; Sp[q][2] = 0.f; }

    for (int tn = 0; tn < NT; tn++) {
        __syncthreads();
        int idx = tc * NT + tn;
        for (int k = t; k < M1 * M2; k += TPB) {
            int j = k / M2, m = k - j * M2;
            int g = m % 25, q = m / 25;
            W2r[j * M2 + g * 4 + q] = W2[(size_t)idx * (M1 * M2) + k];
        }
        for (int k = t; k < M0 * M1; k += TPB) {
            int j = k / M1, m = k - j * M1;
            int g = m % 25, p = m / 25;
            W1r[j * M1 + g * 2 + p] = W1[(size_t)idx * (M0 * M1) + k];
        }
        if (t < M0) { W0s[t] = W0[idx * M0 + t]; b0s[t] = b0[idx * M0 + t]; }
        if (t < M1) { int g = t % 25, p = t / 25; b1r[g * 2 + p] = b1[idx * M1 + t]; }
        if (t < M2) { int g = t % 25, q = t / 25; b2r[g * 4 + q] = b2[idx * M2 + t]; }
        __syncthreads();

        int bs = g_boff[n * NT + tn];
        int be = (tn == NT - 1) ? KNBR : g_boff[n * NT + tn + 1];
        int cnt = be - bs;
        const int* pbase = g_perm + n * KNBR + bs;

        for (int t0 = 0; t0 < cnt; t0 += ET) {
            // ---- Stage 0a: geometry (40 threads) ----
            if (t < ET) {
                int gi = t0 + t;
                float x = 0.f, ax = 0.f, ay = 0.f, az = 0.f;
                if (gi < cnt) {
                    int j = __ldg(&pbase[gi]);
                    float rx = cx - __ldg(&coords[(b * NATOM + j) * 3 + 0]);
                    float ry = cy - __ldg(&coords[(b * NATOM + j) * 3 + 1]);
                    float rz = cz - __ldg(&coords[(b * NATOM + j) * 3 + 2]);
                    float d2 = rx * rx + ry * ry + rz * rz;
                    x = rsqrtf(d2);
                    float i2 = x * x;
                    ax = rx * i2; ay = ry * i2; az = rz * i2;
                }
                xs[t] = x;
                aes[0 * ET + t] = ax;
                aes[1 * ET + t] = ay;
                aes[2 * ET + t] = az;
            }
            __syncthreads();

            float h0v[ER];
            // ---- Stage 0b: layer0 (vectorized xs reads) ----
            if (act) {
                float w0v = W0s[gm], b0v = b0s[gm];
                float4 xA = *(const float4*)(xs + e0);
                float4 xB = *(const float4*)(xs + e0 + 4);
                float xv[8] = {xA.x, xA.y, xA.z, xA.w, xB.x, xB.y, xB.z, xB.w};
#pragma unroll
                for (int e = 0; e < ER; e++)
                    h0v[e] = tanh_m(fmaf(xv[e], w0v, b0v));
                *(float4*)(h0s + gm * HST + e0) = make_float4(h0v[0], h0v[1], h0v[2], h0v[3]);
                *(float4*)(h0s + gm * HST + e0 + 4) = make_float4(h0v[4], h0v[5], h0v[6], h0v[7]);
            }
            __syncthreads();

            // ---- Stage 1: 25->50 GEMM (fully unrolled) + residual-S ----
            if (act) {
                float acc0[ER], acc1[ER];
                float2 bb = *(const float2*)(b1r + gm * 2);
#pragma unroll
                for (int e = 0; e < ER; e++) { acc0[e] = bb.x; acc1[e] = bb.y; }
#pragma unroll
                for (int j = 0; j < M0; j++) {
                    float2 w = *(const float2*)(w1base + j * M1);
                    float4 A = *(const float4*)(h0base + j * HST);
                    float4 Bv = *(const float4*)(h0base + j * HST + 4);
                    acc0[0] = fmaf(w.x, A.x, acc0[0]); acc1[0] = fmaf(w.y, A.x, acc1[0]);
                    acc0[1] = fmaf(w.x, A.y, acc0[1]); acc1[1] = fmaf(w.y, A.y, acc1[1]);
                    acc0[2] = fmaf(w.x, A.z, acc0[2]); acc1[2] = fmaf(w.y, A.z, acc1[2]);
                    acc0[3] = fmaf(w.x, A.w, acc0[3]); acc1[3] = fmaf(w.y, A.w, acc1[3]);
                    acc0[4] = fmaf(w.x, Bv.x, acc0[4]); acc1[4] = fmaf(w.y, Bv.x, acc1[4]);
                    acc0[5] = fmaf(w.x, Bv.y, acc0[5]); acc1[5] = fmaf(w.y, Bv.y, acc1[5]);
                    acc0[6] = fmaf(w.x, Bv.z, acc0[6]); acc1[6] = fmaf(w.y, Bv.z, acc1[6]);
                    acc0[7] = fmaf(w.x, Bv.w, acc0[7]); acc1[7] = fmaf(w.y, Bv.w, acc1[7]);
                }
                float h1v0[ER], h1v1[ER];
#pragma unroll
                for (int e = 0; e < ER; e++) {
                    h1v0[e] = tanh_m(acc0[e]) + h0v[e];
                    h1v1[e] = tanh_m(acc1[e]) + h0v[e];
                }
                *(float4*)(h1s + gm * HST + e0) = make_float4(h1v0[0], h1v0[1], h1v0[2], h1v0[3]);
                *(float4*)(h1s + gm * HST + e0 + 4) = make_float4(h1v0[4], h1v0[5], h1v0[6], h1v0[7]);
                *(float4*)(h1s + (gm + 25) * HST + e0) = make_float4(h1v1[0], h1v1[1], h1v1[2], h1v1[3]);
                *(float4*)(h1s + (gm + 25) * HST + e0 + 4) = make_float4(h1v1[4], h1v1[5], h1v1[6], h1v1[7]);
                // residual S contribution (vectorized aes)
                float4 a0A = *(const float4*)(aeb + 0 * ET);
                float4 a0B = *(const float4*)(aeb + 0 * ET + 4);
                float4 a1A = *(const float4*)(aeb + 1 * ET);
                float4 a1B = *(const float4*)(aeb + 1 * ET + 4);
                float4 a2A = *(const float4*)(aeb + 2 * ET);
                float4 a2B = *(const float4*)(aeb + 2 * ET + 4);
                float a0[8] = {a0A.x, a0A.y, a0A.z, a0A.w, a0B.x, a0B.y, a0B.z, a0B.w};
                float a1[8] = {a1A.x, a1A.y, a1A.z, a1A.w, a1B.x, a1B.y, a1B.z, a1B.w};
                float a2[8] = {a2A.x, a2A.y, a2A.z, a2A.w, a2B.x, a2B.y, a2B.z, a2B.w};
                float R00 = 0.f, R01 = 0.f, R02 = 0.f, R10 = 0.f, R11 = 0.f, R12 = 0.f;
#pragma unroll
                for (int e = 0; e < ER; e++) {
                    R00 = fmaf(a0[e], h1v0[e], R00); R01 = fmaf(a1[e], h1v0[e], R01); R02 = fmaf(a2[e], h1v0[e], R02);
                    R10 = fmaf(a0[e], h1v1[e], R10); R11 = fmaf(a1[e], h1v1[e], R11); R12 = fmaf(a2[e], h1v1[e], R12);
                }
                Sp[0][0] += R00; Sp[0][1] += R01; Sp[0][2] += R02;
                Sp[2][0] += R00; Sp[2][1] += R01; Sp[2][2] += R02;
                Sp[1][0] += R10; Sp[1][1] += R11; Sp[1][2] += R12;
                Sp[3][0] += R10; Sp[3][1] += R11; Sp[3][2] += R12;
            }
            __syncthreads();

            // ---- Stage 2: 50->100 GEMM (5x10 blocked unroll) + tanh-S ----
            if (act) {
                float acc[4][ER];
                float4 bb = *(const float4*)(b2r + gm * 4);
                float bq[4] = {bb.x, bb.y, bb.z, bb.w};
#pragma unroll
                for (int q = 0; q < 4; q++)
#pragma unroll
                    for (int e = 0; e < ER; e++) acc[q][e] = bq[q];
                const float* wp = w2base;
                const float* hp = h1base;
                for (int jb = 0; jb < 5; jb++) {
#pragma unroll
                    for (int u = 0; u < 10; u++) {
                        float4 w = *(const float4*)(wp + u * M2);
                        float4 A = *(const float4*)(hp + u * HST);
                        float4 Bv = *(const float4*)(hp + u * HST + 4);
                        float hv[8] = {A.x, A.y, A.z, A.w, Bv.x, Bv.y, Bv.z, Bv.w};
#pragma unroll
                        for (int e = 0; e < ER; e++) {
                            acc[0][e] = fmaf(w.x, hv[e], acc[0][e]);
                            acc[1][e] = fmaf(w.y, hv[e], acc[1][e]);
                            acc[2][e] = fmaf(w.z, hv[e], acc[2][e]);
                            acc[3][e] = fmaf(w.w, hv[e], acc[3][e]);
                        }
                    }
                    wp += 10 * M2;
                    hp += 10 * HST;
                }
                float4 a0A = *(const float4*)(aeb + 0 * ET);
                float4 a0B = *(const float4*)(aeb + 0 * ET + 4);
                float4 a1A = *(const float4*)(aeb + 1 * ET);
                float4 a1B = *(const float4*)(aeb + 1 * ET + 4);
                float4 a2A = *(const float4*)(aeb + 2 * ET);
                float4 a2B = *(const float4*)(aeb + 2 * ET + 4);
                float a0[8] = {a0A.x, a0A.y, a0A.z, a0A.w, a0B.x, a0B.y, a0B.z, a0B.w};
                float a1[8] = {a1A.x, a1A.y, a1A.z, a1A.w, a1B.x, a1B.y, a1B.z, a1B.w};
                float a2[8] = {a2A.x, a2A.y, a2A.z, a2A.w, a2B.x, a2B.y, a2B.z, a2B.w};
#pragma unroll
                for (int e = 0; e < ER; e++) {
#pragma unroll
                    for (int q = 0; q < 4; q++) {
                        float v = tanh_m(acc[q][e]);
                        Sp[q][0] = fmaf(a0[e], v, Sp[q][0]);
                        Sp[q][1] = fmaf(a1[e], v, Sp[q][1]);
                        Sp[q][2] = fmaf(a2[e], v, Sp[q][2]);
                    }
                }
            }
            __syncthreads();
        }
    }

    // ---- Final reduction (alias onto weight region; guarded by last sync) ----
    float* const Sred = P;                 // [EG][M2*3]
    float* const Sfin = P + EG * M2 * 3;
    if (act) {
#pragma unroll
        for (int q = 0; q < 4; q++) {
            Sred[ge * (M2 * 3) + (gm + 25 * q) * 3 + 0] = Sp[q][0];
            Sred[ge * (M2 * 3) + (gm + 25 * q) * 3 + 1] = Sp[q][1];
            Sred[ge * (M2 * 3) + (gm + 25 * q) * 3 + 2] = Sp[q][2];
        }
    }
    __syncthreads();
    if (t < M2) {
        float s0 = 0.f, s1 = 0.f, s2 = 0.f;
#pragma unroll
        for (int g = 0; g < EG; g++) {
            s0 += Sred[g * (M2 * 3) + t * 3 + 0];
            s1 += Sred[g * (M2 * 3) + t * 3 + 1];
            s2 += Sred[g * (M2 * 3) + t * 3 + 2];
        }
        Sfin[t * 3 + 0] = s0; Sfin[t * 3 + 1] = s1; Sfin[t * 3 + 2] = s2;
    }
    __syncthreads();
    if (t < M2) {
        float s0 = Sfin[t * 3 + 0], s1 = Sfin[t * 3 + 1], s2 = Sfin[t * 3 + 2];
        float4 o;
        o.x = s0 * Sfin[0] + s1 * Sfin[1] + s2 * Sfin[2];
        o.y = s0 * Sfin[3] + s1 * Sfin[4] + s2 * Sfin[5];
        o.z = s0 * Sfin[6] + s1 * Sfin[7] + s2 * Sfin[8];
        o.w = s0 * Sfin[9] + s1 * Sfin[10] + s2 * Sfin[11];
        *(float4*)(out + (size_t)bid * (M2 * 4) + t * 4) = o;
    }
}

extern "C" void kernel_launch(void* const* d_in, const int* in_sizes, int n_in,
                              void* d_out, int out_size)
{
    const float* coords = (const float*)d_in[0];
    const int*   types  = (const int*)d_in[1];
    const float* W0     = (const float*)d_in[2];
    const float* b0     = (const float*)d_in[3];
    const float* W1     = (const float*)d_in[4];
    const float* b1     = (const float*)d_in[5];
    const float* W2     = (const float*)d_in[6];
    const float* b2     = (const float*)d_in[7];
    float* out = (float*)d_out;

    prep_kernel<<<1, NATOM>>>(types);
    main_kernel<<<NB * NATOM, TPB>>>(coords, types, W0, b0, W1, b1, W2, b2, out);
}